// round 7
// baseline (speedup 1.0000x reference)
#include <cuda_runtime.h>
#include <math.h>

#define EPSF 1e-5f

typedef unsigned long long u64;
typedef unsigned int u32;

__device__ __forceinline__ u64 pk2(float a, float b) {
    u64 r;
    asm("mov.b64 %0, {%1, %2};" : "=l"(r) : "r"(__float_as_uint(a)), "r"(__float_as_uint(b)));
    return r;
}
__device__ __forceinline__ u64 ffma2(u64 a, u64 b, u64 c) {
    u64 d;
    asm("fma.rn.f32x2 %0, %1, %2, %3;" : "=l"(d) : "l"(a), "l"(b), "l"(c));
    return d;
}
__device__ __forceinline__ void upk2(u64 v, float& lo, float& hi) {
    unsigned int l, h;
    asm("mov.b64 {%0, %1}, %2;" : "=r"(l), "=r"(h) : "l"(v));
    lo = __uint_as_float(l); hi = __uint_as_float(h);
}
__device__ __forceinline__ float gelu_f(float v) {
    return 0.5f * v * (1.0f + erff(v * 0.70710678118654752f));
}
__device__ __forceinline__ u32 tf32c(float f) {
    u32 r;
    asm("cvt.rna.tf32.f32 %0, %1;" : "=r"(r) : "f"(f));
    return r;
}

/* intermediates */
__device__ float g_x1[4 * 64 * 9216];        /* gelu(bn(involution)) */
__device__ float g_kern[196 * 36864];        /* per-pixel kernels [o=196][pix] */

/* ============ K1a: reduce + span -> kern[196][36864] ============ */
#define A_WR 0        /* [c][16] folded reduce, 1024 */
#define A_BR 1024     /* 16 */
#define A_WS 1040     /* pairs: [o2=98][r=16] x2 floats = 3136 */
#define A_BS 4176     /* 196 (natural pair layout) */
#define A_FLOATS 4372
#define A_BYTES (A_FLOATS * 4)

__global__ void __launch_bounds__(128, 4)
k1a_kern(const float* __restrict__ x,
         const float* __restrict__ w_reduce,
         const float* __restrict__ g_r, const float* __restrict__ b_r,
         const float* __restrict__ m_r, const float* __restrict__ v_r,
         const float* __restrict__ w_span, const float* __restrict__ b_span)
{
    extern __shared__ float sm[];
    const int tid = threadIdx.x;

    for (int i = tid; i < 1024; i += 128) {
        int c = i >> 4, r = i & 15;
        float sc = g_r[r] * rsqrtf(v_r[r] + EPSF);
        sm[A_WR + c * 16 + r] = w_reduce[r * 64 + c] * sc;
    }
    if (tid < 16) {
        float sc = g_r[tid] * rsqrtf(v_r[tid] + EPSF);
        sm[A_BR + tid] = b_r[tid] - m_r[tid] * sc;
    }
    for (int i = tid; i < 98 * 16; i += 128) {   /* WS[o2][r] as float pairs */
        int o2 = i >> 4, r = i & 15;
        sm[A_WS + 2 * i]     = w_span[(2 * o2)     * 16 + r];
        sm[A_WS + 2 * i + 1] = w_span[(2 * o2 + 1) * 16 + r];
    }
    for (int i = tid; i < 196; i += 128) sm[A_BS + i] = b_span[i];
    __syncthreads();

    const int pix = blockIdx.x * 128 + tid;     /* 288*128 = 36864 exactly */
    const int b   = pix / 9216;
    const int hw  = pix - b * 9216;
    const float* xp = x + b * 64 * 9216 + hw;

    /* t = relu(bn(reduce)) */
    u64 t2[8];
    {
        const u64* br2 = (const u64*)(sm + A_BR);
#pragma unroll
        for (int q = 0; q < 8; q++) t2[q] = br2[q];
    }
#pragma unroll 8
    for (int c = 0; c < 64; c++) {
        float xv = xp[c * 9216];
        u64 xv2 = pk2(xv, xv);
        const ulonglong2* w2 = (const ulonglong2*)(sm + A_WR + c * 16);
#pragma unroll
        for (int q = 0; q < 4; q++) {
            ulonglong2 w = w2[q];
            t2[2 * q + 0] = ffma2(w.x, xv2, t2[2 * q + 0]);
            t2[2 * q + 1] = ffma2(w.y, xv2, t2[2 * q + 1]);
        }
    }
    u64 tt2[16];
#pragma unroll
    for (int q = 0; q < 8; q++) {
        float lo, hi; upk2(t2[q], lo, hi);
        lo = fmaxf(lo, 0.f); hi = fmaxf(hi, 0.f);
        tt2[2 * q]     = pk2(lo, lo);
        tt2[2 * q + 1] = pk2(hi, hi);
    }

    /* kern[o] = b_span[o] + sum_r ws[o][r] * t[r], 4 outputs (2 pairs) per iter */
    float* kout = g_kern + pix;
    const u64* bs = (const u64*)(sm + A_BS);
#pragma unroll 1
    for (int o2 = 0; o2 < 98; o2 += 2) {
        u64 a0 = bs[o2];
        u64 a1 = bs[o2 + 1];
        const ulonglong2* wsa = (const ulonglong2*)(sm + A_WS + 32 * o2);
        const ulonglong2* wsb = (const ulonglong2*)(sm + A_WS + 32 * (o2 + 1));
#pragma unroll
        for (int rq = 0; rq < 8; rq++) {
            ulonglong2 wa = wsa[rq];
            ulonglong2 wb = wsb[rq];
            a0 = ffma2(wa.x, tt2[2 * rq],     a0);
            a0 = ffma2(wa.y, tt2[2 * rq + 1], a0);
            a1 = ffma2(wb.x, tt2[2 * rq],     a1);
            a1 = ffma2(wb.y, tt2[2 * rq + 1], a1);
        }
        float e0, e1, e2, e3;
        upk2(a0, e0, e1); upk2(a1, e2, e3);
        kout[(2 * o2 + 0) * 36864] = e0;
        kout[(2 * o2 + 1) * 36864] = e1;
        kout[(2 * o2 + 2) * 36864] = e2;
        kout[(2 * o2 + 3) * 36864] = e3;
    }
}

/* ============ K1b: involution + BN + gelu -> g_x1 ============ */
#define B1W 16
#define B1H 4
#define P2W 22
#define P2H 10
#define P2PIX (P2W * P2H)    /* 220 */

#define B_X   0              /* 64*220 = 14080 */
#define B_SI  14080          /* 64 */
#define B_SHI 14144          /* 64 */
#define B_FLOATS 14208
#define B_BYTES (B_FLOATS * 4)   /* 56832 -> 3 CTAs/SM */

__global__ void __launch_bounds__(256, 3)
k1b_involution(const float* __restrict__ x,
               const float* __restrict__ g_i, const float* __restrict__ b_i,
               const float* __restrict__ m_i, const float* __restrict__ v_i)
{
    extern __shared__ float sm[];
    const int tid = threadIdx.x;
    const int bb  = blockIdx.z;
    const int h0  = blockIdx.y * B1H;
    const int w0  = blockIdx.x * B1W;

    {
        const int xbase = bb * 64 * 9216;
        for (int i = tid; i < 64 * P2PIX; i += 256) {
            int c  = i / P2PIX;
            int p  = i - c * P2PIX;
            int r  = p / P2W;
            int cl = p - r * P2W;
            int gh = h0 + r - 3;
            int gw = w0 + cl - 3;
            float v = 0.f;
            if ((unsigned)gh < 96u && (unsigned)gw < 96u)
                v = x[xbase + c * 9216 + gh * 96 + gw];
            sm[B_X + i] = v;
        }
    }
    if (tid < 64) {
        float sc = g_i[tid] * rsqrtf(v_i[tid] + EPSF);
        sm[B_SI + tid]  = sc;
        sm[B_SHI + tid] = b_i[tid] - m_i[tid] * sc;
    }
    __syncthreads();

    const int px = tid & 63;
    const int g  = tid >> 6;
    const int lx = px & 15;
    const int ly = px >> 4;
    const int hw = (h0 + ly) * 96 + (w0 + lx);
    const int pixg = bb * 9216 + hw;

    /* load this pixel's 49 kernel weights for group g (coalesced) */
    float kr[49];
    {
        const float* kp = g_kern + g * 49 * 36864 + pixg;
#pragma unroll
        for (int kk = 0; kk < 49; kk++) kr[kk] = kp[kk * 36864];
    }

    float* ob = g_x1 + bb * 64 * 9216 + hw;
#pragma unroll 1
    for (int ci = 0; ci < 16; ci++) {
        const int c = g * 16 + ci;
        const float* xb = sm + B_X + c * P2PIX + ly * P2W + lx;
        float a[7];
#pragma unroll
        for (int i = 0; i < 7; i++) {
            float ai = kr[i * 7] * xb[i * P2W];
#pragma unroll
            for (int j = 1; j < 7; j++)
                ai = fmaf(kr[i * 7 + j], xb[i * P2W + j], ai);
            a[i] = ai;
        }
        float acc = ((a[0] + a[1]) + (a[2] + a[3])) + ((a[4] + a[5]) + a[6]);
        float v = fmaf(acc, sm[B_SI + c], sm[B_SHI + c]);
        ob[c * 9216] = gelu_f(v);
    }
}

/* ================= K2: tf32 tensor-core GEMM + bias + gelu ================ */
#define S2_W    0            /* 128*132 (tf32) */
#define S2_CST  16896        /* 128 */
#define S2_Y    17024        /* [2][16][132] */
#define S2_FLOATS 21248
#define S2_BYTES (S2_FLOATS * 4)

__global__ void __launch_bounds__(256, 2)
k2_mma(const float* __restrict__ x,
       const float* __restrict__ w_conv,
       const float* __restrict__ g_c, const float* __restrict__ b_c,
       const float* __restrict__ m_c, const float* __restrict__ v_c,
       const float* __restrict__ w_map, const float* __restrict__ b_map,
       const float* __restrict__ g_m, const float* __restrict__ b_m,
       const float* __restrict__ m_m, const float* __restrict__ v_m,
       float* __restrict__ out)
{
    extern __shared__ float smf[];
    u32* smu = (u32*)smf;
    const int tid = threadIdx.x;

    for (int i = tid; i < 16384; i += 256) {
        int o = i >> 7, k = i & 127;
        float v;
        if (k < 64) v = w_conv[o * 64 + k]        * (g_c[o] * rsqrtf(v_c[o] + EPSF));
        else        v = w_map [o * 64 + (k - 64)] * (g_m[o] * rsqrtf(v_m[o] + EPSF));
        smu[S2_W + o * 132 + k] = tf32c(v);
    }
    if (tid < 128) {
        float sc_c = g_c[tid] * rsqrtf(v_c[tid] + EPSF);
        float sc_m = g_m[tid] * rsqrtf(v_m[tid] + EPSF);
        smf[S2_CST + tid] = (b_c[tid] - m_c[tid] * sc_c)
                          + sc_m * b_map[tid]
                          + (b_m[tid] - m_m[tid] * sc_m);
    }

    const int P0  = blockIdx.x * 128;
    const int b   = P0 / 9216;
    const int off = P0 - b * 9216;

    const int ldr = tid >> 4;
    const int ldc = (tid & 15) * 8;
    const float* x1base = g_x1 + (b * 64) * 9216 + off;
    const float* xbase  = x    + (b * 64) * 9216 + off;

    float4 v0 = *(const float4*)(x1base + ldr * 9216 + ldc);
    float4 v1 = *(const float4*)(x1base + ldr * 9216 + ldc + 4);
    {
        u32* yd = smu + S2_Y + ldr * 132 + ldc;
        yd[0] = tf32c(v0.x); yd[1] = tf32c(v0.y); yd[2] = tf32c(v0.z); yd[3] = tf32c(v0.w);
        yd[4] = tf32c(v1.x); yd[5] = tf32c(v1.y); yd[6] = tf32c(v1.z); yd[7] = tf32c(v1.w);
    }
    __syncthreads();

    const int lane = tid & 31;
    const int gid  = lane >> 2;
    const int tig  = lane & 3;
    const int m0   = (tid >> 5) * 16;

    float c[16][4];
#pragma unroll
    for (int nt = 0; nt < 16; nt++)
#pragma unroll
        for (int q = 0; q < 4; q++) c[nt][q] = 0.f;

#pragma unroll 1
    for (int ch = 0; ch < 8; ch++) {
        if (ch < 7) {
            int kg = (ch + 1) * 16 + ldr;
            const float* src = (kg < 64) ? (x1base + kg * 9216)
                                         : (xbase + (kg - 64) * 9216);
            v0 = *(const float4*)(src + ldc);
            v1 = *(const float4*)(src + ldc + 4);
        }

        const u32* Yb = smu + S2_Y + (ch & 1) * 2112;
#pragma unroll
        for (int ks = 0; ks < 2; ks++) {
            const int kg = ch * 16 + ks * 8;
            u32 a0 = smu[S2_W + (m0 + gid) * 132 + kg + tig];
            u32 a2 = smu[S2_W + (m0 + gid) * 132 + kg + tig + 4];
            u32 a1 = smu[S2_W + (m0 + gid + 8) * 132 + kg + tig];
            u32 a3 = smu[S2_W + (m0 + gid + 8) * 132 + kg + tig + 4];
            const u32* bb = Yb + (ks * 8 + tig) * 132 + gid;
#pragma unroll
            for (int nt = 0; nt < 16; nt++) {
                u32 b0 = bb[nt * 8];
                u32 b1 = bb[nt * 8 + 4 * 132];
                asm volatile(
                    "mma.sync.aligned.m16n8k8.row.col.f32.tf32.tf32.f32 "
                    "{%0,%1,%2,%3}, {%4,%5,%6,%7}, {%8,%9}, {%0,%1,%2,%3};"
                    : "+f"(c[nt][0]), "+f"(c[nt][1]), "+f"(c[nt][2]), "+f"(c[nt][3])
                    : "r"(a0), "r"(a1), "r"(a2), "r"(a3), "r"(b0), "r"(b1));
            }
        }

        if (ch < 7) {
            u32* yd = smu + S2_Y + ((ch + 1) & 1) * 2112 + ldr * 132 + ldc;
            yd[0] = tf32c(v0.x); yd[1] = tf32c(v0.y); yd[2] = tf32c(v0.z); yd[3] = tf32c(v0.w);
            yd[4] = tf32c(v1.x); yd[5] = tf32c(v1.y); yd[6] = tf32c(v1.z); yd[7] = tf32c(v1.w);
        }
        __syncthreads();
    }

    float* ob = out + (b * 128) * 9216 + off;
    const int o0 = m0 + gid;
    const float cst0 = smf[S2_CST + o0];
    const float cst1 = smf[S2_CST + o0 + 8];
#pragma unroll
    for (int nt = 0; nt < 16; nt++) {
        int pxl = nt * 8 + tig * 2;
        float2 r0, r1;
        r0.x = gelu_f(c[nt][0] + cst0);
        r0.y = gelu_f(c[nt][1] + cst0);
        r1.x = gelu_f(c[nt][2] + cst1);
        r1.y = gelu_f(c[nt][3] + cst1);
        *(float2*)(ob + o0 * 9216 + pxl)       = r0;
        *(float2*)(ob + (o0 + 8) * 9216 + pxl) = r1;
    }
}

extern "C" void kernel_launch(void* const* d_in, const int* in_sizes, int n_in,
                              void* d_out, int out_size)
{
    (void)in_sizes; (void)n_in; (void)out_size;
    const float* x        = (const float*)d_in[0];
    const float* w_reduce = (const float*)d_in[1];
    const float* g_r = (const float*)d_in[2];
    const float* b_r = (const float*)d_in[3];
    const float* m_r = (const float*)d_in[4];
    const float* v_r = (const float*)d_in[5];
    const float* w_span = (const float*)d_in[6];
    const float* b_span = (const float*)d_in[7];
    const float* g_i = (const float*)d_in[8];
    const float* b_i = (const float*)d_in[9];
    const float* m_i = (const float*)d_in[10];
    const float* v_i = (const float*)d_in[11];
    const float* w_conv = (const float*)d_in[12];
    const float* g_c = (const float*)d_in[13];
    const float* b_c = (const float*)d_in[14];
    const float* m_c = (const float*)d_in[15];
    const float* v_c = (const float*)d_in[16];
    const float* w_map = (const float*)d_in[17];
    const float* b_map = (const float*)d_in[18];
    const float* g_m = (const float*)d_in[19];
    const float* b_m = (const float*)d_in[20];
    const float* m_m = (const float*)d_in[21];
    const float* v_m = (const float*)d_in[22];
    float* out = (float*)d_out;

    cudaFuncSetAttribute(k1a_kern,       cudaFuncAttributeMaxDynamicSharedMemorySize, A_BYTES);
    cudaFuncSetAttribute(k1b_involution, cudaFuncAttributeMaxDynamicSharedMemorySize, B_BYTES);
    cudaFuncSetAttribute(k2_mma,         cudaFuncAttributeMaxDynamicSharedMemorySize, S2_BYTES);

    k1a_kern<<<288, 128, A_BYTES>>>(x, w_reduce, g_r, b_r, m_r, v_r, w_span, b_span);

    dim3 gb(96 / B1W, 96 / B1H, 4);   /* 6 x 24 x 4 = 576 */
    k1b_involution<<<gb, 256, B_BYTES>>>(x, g_i, b_i, m_i, v_i);

    k2_mma<<<288, 256, S2_BYTES>>>(x, w_conv, g_c, b_c, m_c, v_c,
                                   w_map, b_map, g_m, b_m, m_m, v_m, out);
}